// round 12
// baseline (speedup 1.0000x reference)
#include <cuda_runtime.h>
#include <cstdint>

#define H    50
#define G4   200
#define E    4
#define BSZ  512
#define NTH  448
#define NCH  7       // ulonglong2 chunks per K-half
#define HPAD 56

typedef unsigned long long u64;

__device__ __forceinline__ void fma2(u64 &d, u64 a, u64 b) {
    asm("fma.rn.f32x2 %0, %1, %2, %0;" : "+l"(d) : "l"(a), "l"(b));
}
__device__ __forceinline__ float lo32(u64 a){ return __uint_as_float((unsigned)a); }
__device__ __forceinline__ float hi32(u64 a){ return __uint_as_float((unsigned)(a >> 32)); }
__device__ __forceinline__ float hsum2(u64 a){ return lo32(a) + hi32(a); }
__device__ __forceinline__ u64 pk2(float lo, float hi) {
    return ((u64)__float_as_uint(hi) << 32) | (u64)__float_as_uint(lo);
}
__device__ __forceinline__ float sigf(float v) {
    return __fdividef(1.0f, 1.0f + __expf(-v));
}
__device__ __forceinline__ float tanhf_(float v) {
    return 1.0f - __fdividef(2.0f, 1.0f + __expf(2.0f * v));
}

__global__ void __launch_bounds__(NTH, 1) sinelstm_kernel(
    const float* __restrict__ x,
    const float* __restrict__ W_ih1, const float* __restrict__ W_hh1,
    const float* __restrict__ b_ih1, const float* __restrict__ b_hh1,
    const float* __restrict__ W_ih2, const float* __restrict__ W_hh2,
    const float* __restrict__ b_ih2, const float* __restrict__ b_hh2,
    const float* __restrict__ W_lin, const float* __restrict__ b_lin,
    float* __restrict__ out, int T, int TP)
{
    __shared__ __align__(16) float h1s[E][HPAD];
    __shared__ __align__(16) float h2s[E][HPAD];
    __shared__ u64  g1[E][G4];          // per (e,row): halves packed (hf0=lo, hf1=hi)
    __shared__ u64  g2[E][G4];
    __shared__ __align__(16) float obuf[E][52];
    __shared__ float outs_s[E];

    const int  t    = threadIdx.x;
    const int  base = blockIdx.x * E;
    const int  pr   = t >> 1;           // gate row
    const int  hf   = t & 1;            // K-half
    const bool dotth = (t < 400);       // rows 0..199

    // ---- register-resident weights (row pr, half hf) ----
    u64 w1p[2 * NCH], wa[2 * NCH], wb[2 * NCH];
    float bias1 = 0.f, bias2 = 0.f;
    {
        const bool row_ok = dotth;
        #pragma unroll
        for (int p = 0; p < 2 * NCH; p++) {
            int kk = 2 * (hf * 2 * NCH + p);
            float a0 = (row_ok && kk     < H) ? W_hh1[pr * H + kk]     : 0.f;
            float a1 = (row_ok && kk + 1 < H) ? W_hh1[pr * H + kk + 1] : 0.f;
            w1p[p] = pk2(a0, a1);
            float c0 = (row_ok && kk     < H) ? W_ih2[pr * H + kk]     : 0.f;
            float c1v= (row_ok && kk + 1 < H) ? W_ih2[pr * H + kk + 1] : 0.f;
            wa[p] = pk2(c0, c1v);
            float d0 = (row_ok && kk     < H) ? W_hh2[pr * H + kk]     : 0.f;
            float d1 = (row_ok && kk + 1 < H) ? W_hh2[pr * H + kk + 1] : 0.f;
            wb[p] = pk2(d0, d1);
        }
        if (row_ok) {
            bias1 = b_ih1[pr] + b_hh1[pr];
            bias2 = b_ih2[pr] + b_hh2[pr];
        }
    }

    // ---- act roles ----
    const bool a1role = (t < 100);                 // act1: unit uu, e = 2*g + eL
    const bool a2role = (t >= 100) && (t < 200);   // act2
    const int  eL = (a1role ? t : t - 100) / 50;   // element within group
    const int  uu = (a1role ? t : t - 100) % 50;
    float wxi = 0.f, wxf = 0.f, wxg = 0.f, wxo = 0.f, wlin_u = 0.f;
    if (a1role) {
        wxi = W_ih1[uu];          wxf = W_ih1[uu + H];
        wxg = W_ih1[uu + 2 * H];  wxo = W_ih1[uu + 3 * H];
    }
    if (a2role) wlin_u = __ldg(&W_lin[uu]);
    const float blin = b_lin[0];
    float c1g[2] = {0.f, 0.f};     // act1 threads: c1 per group
    float c2g[2] = {0.f, 0.f};     // act2 threads: c2 per group

    const bool fin = (t >= 440) && (t < 444);
    const int  fe  = t - 440;

    // ---- init ----
    for (int i = t; i < E * HPAD; i += NTH) { ((float*)h1s)[i] = 0.f; ((float*)h2s)[i] = 0.f; }
    for (int i = t; i < E * 52;   i += NTH) ((float*)obuf)[i] = 0.f;
    __syncthreads();

    // ---- lambdas ----
    auto dots2 = [&](int b, bool wg1, bool wg2) {   // group base b: elements b, b+1
        #pragma unroll
        for (int ee = 0; ee < 2; ee++) {
            const int e = b + ee;
            const ulonglong2* h1v = (const ulonglong2*)(&h1s[e][hf * 4 * NCH]);
            const ulonglong2* h2v = (const ulonglong2*)(&h2s[e][hf * 4 * NCH]);
            u64 a1 = 0ull, a2 = 0ull;
            if (wg1 && wg2) {
                #pragma unroll
                for (int q = 0; q < NCH; q++) {
                    ulonglong2 hc = h1v[q];
                    fma2(a1, w1p[2 * q],     hc.x); fma2(a1, w1p[2 * q + 1], hc.y);
                    fma2(a2, wa[2 * q],      hc.x); fma2(a2, wa[2 * q + 1],  hc.y);
                }
            } else if (wg1) {
                #pragma unroll
                for (int q = 0; q < NCH; q++) {
                    ulonglong2 hc = h1v[q];
                    fma2(a1, w1p[2 * q],     hc.x); fma2(a1, w1p[2 * q + 1], hc.y);
                }
            } else if (wg2) {
                #pragma unroll
                for (int q = 0; q < NCH; q++) {
                    ulonglong2 hc = h1v[q];
                    fma2(a2, wa[2 * q],      hc.x); fma2(a2, wa[2 * q + 1],  hc.y);
                }
            }
            if (wg2) {
                #pragma unroll
                for (int q = 0; q < NCH; q++) {
                    ulonglong2 hc = h2v[q];
                    fma2(a2, wb[2 * q],      hc.x); fma2(a2, wb[2 * q + 1],  hc.y);
                }
            }
            if (wg1) {
                float s1 = hsum2(a1);
                if (hf == 0) s1 += bias1;
                ((float*)&g1[e][pr])[hf] = s1;
            }
            if (wg2) {
                float s2 = hsum2(a2);
                if (hf == 0) s2 += bias2;
                ((float*)&g2[e][pr])[hf] = s2;
            }
        }
    };
    auto act1 = [&](int g, float xv) {
        if (a1role) {
            const int e = 2 * g + eL;
            float gi = hsum2(g1[e][uu])         + wxi * xv;
            float gf = hsum2(g1[e][H + uu])     + wxf * xv;
            float gg = hsum2(g1[e][2 * H + uu]) + wxg * xv;
            float go = hsum2(g1[e][3 * H + uu]) + wxo * xv;
            float c = c1g[g];
            c = sigf(gf) * c + sigf(gi) * tanhf_(gg);
            c1g[g] = c;
            h1s[e][uu] = sigf(go) * tanhf_(c);
        }
    };
    auto act2 = [&](int g) {
        if (a2role) {
            const int e = 2 * g + eL;
            float gi = hsum2(g2[e][uu]);
            float gf = hsum2(g2[e][H + uu]);
            float gg = hsum2(g2[e][2 * H + uu]);
            float go = hsum2(g2[e][3 * H + uu]);
            float c = c2g[g];
            c = sigf(gf) * c + sigf(gi) * tanhf_(gg);
            c2g[g] = c;
            float h2 = sigf(go) * tanhf_(c);
            h2s[e][uu] = h2;
            obuf[e][uu] = wlin_u * h2;
        }
    };
    auto finalizeG = [&](int grp, int step, bool seed) {
        if (fin && (fe >> 1) == grp && step >= 0) {
            const float4* ob = (const float4*)obuf[fe];
            float a0 = 0.f, a1 = 0.f, a2 = 0.f, a3 = 0.f;
            #pragma unroll
            for (int q = 0; q < 13; q += 4) {
                float4 v0 = ob[q];     a0 += v0.x + v0.y + v0.z + v0.w;
                if (q + 1 < 13) { float4 v1 = ob[q + 1]; a1 += v1.x + v1.y + v1.z + v1.w; }
                if (q + 2 < 13) { float4 v2 = ob[q + 2]; a2 += v2.x + v2.y + v2.z + v2.w; }
                if (q + 3 < 13) { float4 v3 = ob[q + 3]; a3 += v3.x + v3.y + v3.z + v3.w; }
            }
            float o = (a0 + a1) + (a2 + a3) + blin;
            out[(size_t)(base + fe) * TP + step] = o;
            if (seed) outs_s[fe] = o;
        }
    };

    // ================= pipelined main loop =================
    // R_A(s): dots_A(s) [g1A(s), g2A(s-1)] || act1B(s-1), act2B(s-2) || finalize A(s-2)
    // R_B(s): dots_B(s)                    || act1A(s),   act2A(s-1) || finalize B(s-2)
    float xvB_prev = 0.f;
    for (int s = 0; s <= T; s++) {
        float xvA = 0.f, xvB_cur = 0.f;
        if (a1role && s < T) {
            xvA     = __ldg(&x[(size_t)(base + eL) * T + s]);        // used this iter (R_B)
            xvB_cur = __ldg(&x[(size_t)(base + 2 + eL) * T + s]);    // used next iter (R_A)
        }
        // ---- R_A(s) ----
        if (dotth) dots2(0, s < T, s >= 1);
        else       finalizeG(0, s - 2, false);
        if (s >= 1) act1(1, xvB_prev);
        if (s >= 2) act2(1);
        __syncthreads();
        // ---- R_B(s) ----
        if (dotth) dots2(2, s < T, s >= 1);
        else       finalizeG(1, s - 2, false);
        if (s < T)  act1(0, xvA);
        if (s >= 1) act2(0);
        __syncthreads();
        xvB_prev = xvB_cur;
    }

    // ---- drain: act2B(T-1); finalize A(T-1), B(T-1); seed feedback ----
    act2(1);
    finalizeG(0, T - 1, true);
    __syncthreads();
    finalizeG(1, T - 1, true);
    __syncthreads();

    // ================= predict loop: strict ordering =================
    for (int s = T; s < TP; s++) {
        if (dotth) { dots2(0, true, false); dots2(2, true, false); }
        __syncthreads();
        act1(0, outs_s[eL]);
        act1(1, outs_s[2 + eL]);
        __syncthreads();
        if (dotth) { dots2(0, false, true); dots2(2, false, true); }
        __syncthreads();
        act2(0);
        act2(1);
        __syncthreads();
        finalizeG(0, s, true);
        finalizeG(1, s, true);
        __syncthreads();
    }
}

extern "C" void kernel_launch(void* const* d_in, const int* in_sizes, int n_in,
                              void* d_out, int out_size) {
    const float* x     = (const float*)d_in[0];
    const float* W_ih1 = (const float*)d_in[1];
    const float* W_hh1 = (const float*)d_in[2];
    const float* b_ih1 = (const float*)d_in[3];
    const float* b_hh1 = (const float*)d_in[4];
    const float* W_ih2 = (const float*)d_in[5];
    const float* W_hh2 = (const float*)d_in[6];
    const float* b_ih2 = (const float*)d_in[7];
    const float* b_hh2 = (const float*)d_in[8];
    const float* W_lin = (const float*)d_in[9];
    const float* b_lin = (const float*)d_in[10];

    int T  = in_sizes[0] / BSZ;      // 1024
    int TP = out_size   / BSZ;       // 1056

    sinelstm_kernel<<<BSZ / E, NTH>>>(
        x, W_ih1, W_hh1, b_ih1, b_hh1,
        W_ih2, W_hh2, b_ih2, b_hh2,
        W_lin, b_lin, (float*)d_out, T, TP);
}